// round 1
// baseline (speedup 1.0000x reference)
#include <cuda_runtime.h>
#include <math.h>

#define B_     64
#define S_EN_  50
#define S_DE_  50
#define H_     32
#define EMB_E_ 64
#define EMB_D_ 32
#define DE_V_  19000
#define VPB    128
#define NBLK   ((DE_V_ + VPB - 1) / VPB)   // 149
#define NTH    256
#define PSTRIDE 152

// ---------------- device-global scratch (no allocations allowed) ----------------
__device__ unsigned long long g_part[B_ * PSTRIDE];   // per-(row, block) argmax partials
__device__ unsigned long long g_hT2[H_ * B_];         // h packed (h,h) transposed [k][b]
__device__ unsigned g_cnt = 0;
__device__ unsigned g_gen = 0;

// ---------------- f32x2 helpers ----------------
__device__ __forceinline__ unsigned long long pack2(float lo, float hi) {
    unsigned long long r;
    asm("mov.b64 %0, {%1, %2};" : "=l"(r) : "f"(lo), "f"(hi));
    return r;
}
__device__ __forceinline__ float2 unpack2(unsigned long long v) {
    float2 r;
    asm("mov.b64 {%0, %1}, %2;" : "=f"(r.x), "=f"(r.y) : "l"(v));
    return r;
}
__device__ __forceinline__ void fma2(unsigned long long& d, unsigned long long a, unsigned long long b) {
    asm("fma.rn.f32x2 %0, %1, %2, %0;" : "+l"(d) : "l"(a), "l"(b));
}

__device__ __forceinline__ float sigmoidf_(float x) { return 1.0f / (1.0f + expf(-x)); }

// argmax key: larger key == (bigger value, then smaller index) -> matches jnp.argmax
__device__ __forceinline__ unsigned long long amax_key(float f, int v) {
    unsigned u = __float_as_uint(f);
    u = (u & 0x80000000u) ? ~u : (u | 0x80000000u);
    return ((unsigned long long)u << 32) | (unsigned long long)(0xFFFFFFFFu - (unsigned)v);
}

// ---------------- replay-safe grid barrier ----------------
__device__ __forceinline__ void grid_barrier() {
    __threadfence();          // gpu-scope fence: flushes/invalidates L1D (B300), publishes our writes
    __syncthreads();
    if (threadIdx.x == 0) {
        unsigned my = *(volatile unsigned*)&g_gen;
        __threadfence();      // compiler+mem barrier: 'my' read strictly before arrival
        if (atomicAdd(&g_cnt, 1u) == NBLK - 1) {
            g_cnt = 0;
            __threadfence();
            atomicAdd(&g_gen, 1u);
        } else {
            while (*(volatile unsigned*)&g_gen == my) { __nanosleep(32); }
        }
    }
    __syncthreads();
}

__global__ void __launch_bounds__(NTH, 2)
seq2seq_kernel(const int* __restrict__ en_batch, const int* __restrict__ en_lens,
               const int* __restrict__ de_batch,
               const float* __restrict__ en_emb,
               const float* __restrict__ eWih, const float* __restrict__ eWhh,
               const float* __restrict__ ebih, const float* __restrict__ ebhh,
               const float* __restrict__ de_emb,
               const float* __restrict__ dWih, const float* __restrict__ dWhh,
               const float* __restrict__ dbih, const float* __restrict__ dbhh,
               const float* __restrict__ fcW, const float* __restrict__ fcb,
               float* __restrict__ out)
{
    __shared__ __align__(16) float sW[H_][VPB];            // fc_W tile [k][v-local], 16KB
    __shared__ unsigned long long sWb2[VPB / 2];           // fc_b pairs
    __shared__ unsigned long long sH2[H_][B_];             // (h,h) packed, [k][b], 16KB
    __shared__ unsigned long long sBest[B_];
    __shared__ unsigned long long sRed[8];
    __shared__ float sPart[2][4 * H_];
    __shared__ float sBias[4 * H_];
    __shared__ float sX[EMB_E_];
    __shared__ float s_h[H_], s_c[H_];
    __shared__ int s_tok;

    const int tid = threadIdx.x;
    const int bk  = blockIdx.x;
    const int v0  = bk * VPB;
    const int nv  = (DE_V_ - v0 < VPB) ? (DE_V_ - v0) : VPB;

    // ---------- one-time: load fc_W tile (zero-padded), fc_b pairs, zero out[:,0,:] ----------
    for (int i = tid; i < H_ * VPB; i += NTH) {
        int v = i >> 5, k = i & 31;                 // coalesced over fcW
        float w = 0.0f;
        if (v0 + v < DE_V_) w = fcW[(size_t)(v0 + v) * H_ + k];
        sW[k][v] = w;
    }
    for (int i = tid; i < VPB / 2; i += NTH) {
        float lo = (v0 + 2 * i     < DE_V_) ? fcb[v0 + 2 * i]     : 0.0f;
        float hi = (v0 + 2 * i + 1 < DE_V_) ? fcb[v0 + 2 * i + 1] : 0.0f;
        sWb2[i] = pack2(lo, hi);
    }
    for (int i = tid; i < B_ * VPB; i += NTH) {
        int b = i / VPB, v = i % VPB;
        if (v < nv) out[(size_t)(b * S_DE_) * DE_V_ + v0 + v] = 0.0f;
    }

    float wreg[48];
    const int jg = tid & 127;       // gate index
    const int hf = tid >> 7;        // which half of the k-range

    // ---------- encoder: blocks 0..63, one batch row each, weights in registers ----------
    if (bk < B_) {
        // half0: Wih k[0:32] + Whh k[0:16] ; half1: Wih k[32:64] + Whh k[16:32]
        #pragma unroll
        for (int k = 0; k < 32; k++) wreg[k] = eWih[jg * EMB_E_ + hf * 32 + k];
        #pragma unroll
        for (int k = 0; k < 16; k++) wreg[32 + k] = eWhh[jg * H_ + hf * 16 + k];
        if (tid < 4 * H_) sBias[tid] = ebih[tid] + ebhh[tid];
        if (tid < H_) { s_h[tid] = 0.0f; s_c[tid] = 0.0f; }
        __syncthreads();

        const int b   = bk;
        const int len = en_lens[b];
        for (int t = 0; t < S_EN_; t++) {
            if (tid < EMB_E_) {
                int tok = en_batch[b * S_EN_ + t];
                sX[tid] = en_emb[(size_t)tok * EMB_E_ + tid];
            }
            __syncthreads();
            {
                float p = 0.0f;
                #pragma unroll
                for (int k = 0; k < 32; k++) p += sX[hf * 32 + k] * wreg[k];
                #pragma unroll
                for (int k = 0; k < 16; k++) p += s_h[hf * 16 + k] * wreg[32 + k];
                sPart[hf][jg] = p;
            }
            __syncthreads();
            if (tid < H_ && t < len) {
                float gi = sPart[0][tid]          + sPart[1][tid]          + sBias[tid];
                float gf = sPart[0][H_ + tid]     + sPart[1][H_ + tid]     + sBias[H_ + tid];
                float gg = sPart[0][2 * H_ + tid] + sPart[1][2 * H_ + tid] + sBias[2 * H_ + tid];
                float go = sPart[0][3 * H_ + tid] + sPart[1][3 * H_ + tid] + sBias[3 * H_ + tid];
                float ig = sigmoidf_(gi), fg = sigmoidf_(gf), og = sigmoidf_(go);
                float c  = fg * s_c[tid] + ig * tanhf(gg);
                s_c[tid] = c;
                s_h[tid] = og * tanhf(c);
            }
            __syncthreads();
        }

        // swap to decoder LSTM weights: half0 = Wih row, half1 = Whh row (32 each)
        #pragma unroll
        for (int k = 0; k < 32; k++)
            wreg[k] = hf ? dWhh[jg * H_ + k] : dWih[jg * EMB_D_ + k];
        if (tid < 4 * H_) sBias[tid] = dbih[tid] + dbhh[tid];
        __syncthreads();
    }

    grid_barrier();

    const int bq  = tid & 15;       // b-lane (b = bq + 16*i)
    const int vq  = tid >> 4;       // v-octet
    const int vl0 = vq * 8;

    for (int s = 1; s < S_DE_; s++) {
        // ---------------- phase A: decoder LSTM (blocks 0..63) ----------------
        if (bk < B_) {
            const int b = bk;
            int tok;
            if (s == 1) {
                tok = de_batch[b * S_DE_];
            } else {
                unsigned long long key = (tid < NBLK) ? g_part[b * PSTRIDE + tid] : 0ull;
                #pragma unroll
                for (int o = 16; o > 0; o >>= 1) {
                    unsigned long long oth = __shfl_down_sync(0xffffffffu, key, o);
                    if (oth > key) key = oth;
                }
                if ((tid & 31) == 0) sRed[tid >> 5] = key;
                __syncthreads();
                if (tid < 8) {
                    key = sRed[tid];
                    #pragma unroll
                    for (int o = 4; o > 0; o >>= 1) {
                        unsigned long long oth = __shfl_down_sync(0xffu, key, o);
                        if (oth > key) key = oth;
                    }
                    if (tid == 0) s_tok = (int)(0xFFFFFFFFu - (unsigned)(key & 0xFFFFFFFFull));
                }
                __syncthreads();
                tok = s_tok;
            }
            if (tid < EMB_D_) sX[tid] = de_emb[(size_t)tok * EMB_D_ + tid];
            __syncthreads();
            {
                const float* src = hf ? s_h : sX;
                float p = 0.0f;
                #pragma unroll
                for (int k = 0; k < 32; k++) p += src[k] * wreg[k];
                sPart[hf][jg] = p;
            }
            __syncthreads();
            if (tid < H_) {
                float gi = sPart[0][tid]          + sPart[1][tid]          + sBias[tid];
                float gf = sPart[0][H_ + tid]     + sPart[1][H_ + tid]     + sBias[H_ + tid];
                float gg = sPart[0][2 * H_ + tid] + sPart[1][2 * H_ + tid] + sBias[2 * H_ + tid];
                float go = sPart[0][3 * H_ + tid] + sPart[1][3 * H_ + tid] + sBias[3 * H_ + tid];
                float ig = sigmoidf_(gi), fg = sigmoidf_(gf), og = sigmoidf_(go);
                float c  = fg * s_c[tid] + ig * tanhf(gg);
                s_c[tid] = c;
                float h  = og * tanhf(c);
                s_h[tid] = h;
                g_hT2[tid * B_ + b] = pack2(h, h);   // (h,h) packed, transposed
            }
        }
        grid_barrier();

        // ---------------- phase B: logits tile + partial argmax (all blocks) ----------------
        {
            unsigned long long* dst = &sH2[0][0];
            for (int i = tid; i < H_ * B_; i += NTH) dst[i] = g_hT2[i];
            if (tid < B_) sBest[tid] = 0ull;
        }
        __syncthreads();

        unsigned long long acc[4][4];
        #pragma unroll
        for (int i = 0; i < 4; i++)
            #pragma unroll
            for (int j = 0; j < 4; j++) acc[i][j] = sWb2[vq * 4 + j];

        #pragma unroll 8
        for (int k = 0; k < H_; k++) {
            const unsigned long long* w64 = (const unsigned long long*)&sW[k][0];
            unsigned long long w0 = w64[vq * 4 + 0];
            unsigned long long w1 = w64[vq * 4 + 1];
            unsigned long long w2 = w64[vq * 4 + 2];
            unsigned long long w3 = w64[vq * 4 + 3];
            #pragma unroll
            for (int i = 0; i < 4; i++) {
                unsigned long long hh = sH2[k][bq + 16 * i];   // stride-16 b layout: conflict-free
                fma2(acc[i][0], hh, w0);
                fma2(acc[i][1], hh, w1);
                fma2(acc[i][2], hh, w2);
                fma2(acc[i][3], hh, w3);
            }
        }

        if (vl0 < nv) {   // nv is a multiple of 8 shortfall-wise (56 on the last block)
            #pragma unroll
            for (int i = 0; i < 4; i++) {
                const int b = bq + 16 * i;
                float2 p0 = unpack2(acc[i][0]);
                float2 p1 = unpack2(acc[i][1]);
                float2 p2 = unpack2(acc[i][2]);
                float2 p3 = unpack2(acc[i][3]);
                float4* orow = (float4*)(out + ((size_t)b * S_DE_ + s) * DE_V_ + v0 + vl0);
                orow[0] = make_float4(p0.x, p0.y, p1.x, p1.y);
                orow[1] = make_float4(p2.x, p2.y, p3.x, p3.y);
                const int vb = v0 + vl0;
                unsigned long long best = amax_key(p0.x, vb);
                unsigned long long k2;
                k2 = amax_key(p0.y, vb + 1); if (k2 > best) best = k2;
                k2 = amax_key(p1.x, vb + 2); if (k2 > best) best = k2;
                k2 = amax_key(p1.y, vb + 3); if (k2 > best) best = k2;
                k2 = amax_key(p2.x, vb + 4); if (k2 > best) best = k2;
                k2 = amax_key(p2.y, vb + 5); if (k2 > best) best = k2;
                k2 = amax_key(p3.x, vb + 6); if (k2 > best) best = k2;
                k2 = amax_key(p3.y, vb + 7); if (k2 > best) best = k2;
                atomicMax(&sBest[b], best);
            }
        }
        __syncthreads();
        if (tid < B_) g_part[tid * PSTRIDE + bk] = sBest[tid];
        grid_barrier();
    }
}

extern "C" void kernel_launch(void* const* d_in, const int* in_sizes, int n_in,
                              void* d_out, int out_size) {
    const int*   en_batch = (const int*)d_in[0];
    const int*   en_lens  = (const int*)d_in[1];
    const int*   de_batch = (const int*)d_in[2];
    const float* en_emb   = (const float*)d_in[3];
    const float* eWih     = (const float*)d_in[4];
    const float* eWhh     = (const float*)d_in[5];
    const float* ebih     = (const float*)d_in[6];
    const float* ebhh     = (const float*)d_in[7];
    const float* de_emb   = (const float*)d_in[8];
    const float* dWih     = (const float*)d_in[9];
    const float* dWhh     = (const float*)d_in[10];
    const float* dbih     = (const float*)d_in[11];
    const float* dbhh     = (const float*)d_in[12];
    const float* fcW      = (const float*)d_in[13];
    const float* fcb      = (const float*)d_in[14];

    seq2seq_kernel<<<NBLK, NTH>>>(en_batch, en_lens, de_batch, en_emb,
                                  eWih, eWhh, ebih, ebhh,
                                  de_emb, dWih, dWhh, dbih, dbhh,
                                  fcW, fcb, (float*)d_out);
}

// round 4
// speedup vs baseline: 1.1821x; 1.1821x over previous
#include <cuda_runtime.h>
#include <math.h>

#define B_     64
#define S_EN_  50
#define S_DE_  50
#define H_     32
#define EMB_E_ 64
#define EMB_D_ 32
#define DE_V_  19000
#define VPB    128
#define NBLK   ((DE_V_ + VPB - 1) / VPB)   // 149
#define NTH    256

// ---------------- device-global scratch (no allocations allowed) ----------------
__device__ unsigned long long g_best[S_DE_ * B_ * 2];   // per-step, per-row argmax keys (pad 2)
__device__ float g_h[H_ * B_];                          // h transposed [k][b]
__device__ unsigned g_hdone[S_DE_ + 1];                 // per-step: 64 LSTM arrivals
__device__ unsigned g_done[S_DE_ + 1];                  // per-step: 149 GEMM arrivals
__device__ unsigned g_cnt = 0, g_gen = 0;               // init barrier only

// ---------------- helpers ----------------
__device__ __forceinline__ unsigned long long pack2(float lo, float hi) {
    unsigned long long r;
    asm("mov.b64 %0, {%1, %2};" : "=l"(r) : "f"(lo), "f"(hi));
    return r;
}
__device__ __forceinline__ float2 unpack2(unsigned long long v) {
    float2 r;
    asm("mov.b64 {%0, %1}, %2;" : "=f"(r.x), "=f"(r.y) : "l"(v));
    return r;
}
__device__ __forceinline__ void fma2(unsigned long long& d, unsigned long long a, unsigned long long b) {
    asm("fma.rn.f32x2 %0, %1, %2, %0;" : "+l"(d) : "l"(a), "l"(b));
}
__device__ __forceinline__ float sigmoidf_(float x) { return 1.0f / (1.0f + expf(-x)); }

// larger key == (bigger value, then smaller index) -> matches jnp.argmax
__device__ __forceinline__ unsigned long long amax_key(float f, int v) {
    unsigned u = __float_as_uint(f);
    u = (u & 0x80000000u) ? ~u : (u | 0x80000000u);
    return ((unsigned long long)u << 32) | (unsigned long long)(0xFFFFFFFFu - (unsigned)v);
}
__device__ __forceinline__ unsigned ld_acq(const unsigned* p) {
    unsigned v;
    asm volatile("ld.acquire.gpu.global.u32 %0, [%1];" : "=r"(v) : "l"(p) : "memory");
    return v;
}

// one-time init barrier (replay-safe: g_cnt returns to 0, g_gen monotonic)
__device__ __forceinline__ void grid_barrier() {
    __threadfence();
    __syncthreads();
    if (threadIdx.x == 0) {
        unsigned my = *(volatile unsigned*)&g_gen;
        __threadfence();
        if (atomicAdd(&g_cnt, 1u) == NBLK - 1) {
            g_cnt = 0;
            __threadfence();
            atomicAdd(&g_gen, 1u);
        } else {
            while (*(volatile unsigned*)&g_gen == my) { __nanosleep(32); }
        }
    }
    __syncthreads();
}

__global__ void __launch_bounds__(NTH, 2)
seq2seq_kernel(const int* __restrict__ en_batch, const int* __restrict__ en_lens,
               const int* __restrict__ de_batch,
               const float* __restrict__ en_emb,
               const float* __restrict__ eWih, const float* __restrict__ eWhh,
               const float* __restrict__ ebih, const float* __restrict__ ebhh,
               const float* __restrict__ de_emb,
               const float* __restrict__ dWih, const float* __restrict__ dWhh,
               const float* __restrict__ dbih, const float* __restrict__ dbhh,
               const float* __restrict__ fcW, const float* __restrict__ fcb,
               float* __restrict__ out)
{
    __shared__ __align__(16) float sW[H_][VPB];            // fc_W tile [k][v-local]
    __shared__ unsigned long long sWb2[VPB / 2];           // fc_b pairs
    __shared__ unsigned long long sH2[H_][B_];             // (h,h) packed, [k][b]
    __shared__ unsigned long long sBest[B_];
    __shared__ float sPart[2][4 * H_];
    __shared__ float sBias[4 * H_];
    __shared__ float sX[EMB_E_];
    __shared__ float s_h[H_], s_c[H_];
    __shared__ int s_tok;

    const int tid = threadIdx.x;
    const int bk  = blockIdx.x;
    const int v0  = bk * VPB;
    const int nv  = (DE_V_ - v0 < VPB) ? (DE_V_ - v0) : VPB;

    // ---------- phase 0: fc tile load, out[:,0,:] zero, sync-array zero ----------
    for (int i = tid; i < H_ * VPB; i += NTH) {
        int v = i >> 5, k = i & 31;
        float w = 0.0f;
        if (v0 + v < DE_V_) w = fcW[(size_t)(v0 + v) * H_ + k];
        sW[k][v] = w;
    }
    for (int i = tid; i < VPB / 2; i += NTH) {
        float lo = (v0 + 2 * i     < DE_V_) ? fcb[v0 + 2 * i]     : 0.0f;
        float hi = (v0 + 2 * i + 1 < DE_V_) ? fcb[v0 + 2 * i + 1] : 0.0f;
        sWb2[i] = pack2(lo, hi);
    }
    for (int i = tid; i < B_ * VPB; i += NTH) {
        int b = i / VPB, v = i % VPB;
        if (v < nv) out[(size_t)(b * S_DE_) * DE_V_ + v0 + v] = 0.0f;
    }
    {   // zero per-step sync state (graph replay safety)
        int gt = bk * NTH + tid;
        if (gt < S_DE_ * B_ * 2) g_best[gt] = 0ull;
        if (gt < S_DE_ + 1) { g_hdone[gt] = 0u; g_done[gt] = 0u; }
    }

    float wreg[48];
    const int jg = tid & 127;       // gate index
    const int hf = tid >> 7;        // which half of the k-range

    grid_barrier();                  // zeroing + tiles visible chip-wide

    // ---------- encoder + first decoder LSTM: blocks 0..63 ----------
    if (bk < B_) {
        #pragma unroll
        for (int k = 0; k < 32; k++) wreg[k] = eWih[jg * EMB_E_ + hf * 32 + k];
        #pragma unroll
        for (int k = 0; k < 16; k++) wreg[32 + k] = eWhh[jg * H_ + hf * 16 + k];
        if (tid < 4 * H_) sBias[tid] = ebih[tid] + ebhh[tid];
        if (tid < H_) { s_h[tid] = 0.0f; s_c[tid] = 0.0f; }
        __syncthreads();

        const int b   = bk;
        const int len = en_lens[b];
        for (int t = 0; t < S_EN_; t++) {
            if (tid < EMB_E_) {
                int tok = en_batch[b * S_EN_ + t];
                sX[tid] = en_emb[(size_t)tok * EMB_E_ + tid];
            }
            __syncthreads();
            {
                float p = 0.0f;
                #pragma unroll
                for (int k = 0; k < 32; k++) p += sX[hf * 32 + k] * wreg[k];
                #pragma unroll
                for (int k = 0; k < 16; k++) p += s_h[hf * 16 + k] * wreg[32 + k];
                sPart[hf][jg] = p;
            }
            __syncthreads();
            if (tid < H_ && t < len) {
                float gi = sPart[0][tid]          + sPart[1][tid]          + sBias[tid];
                float gf = sPart[0][H_ + tid]     + sPart[1][H_ + tid]     + sBias[H_ + tid];
                float gg = sPart[0][2 * H_ + tid] + sPart[1][2 * H_ + tid] + sBias[2 * H_ + tid];
                float go = sPart[0][3 * H_ + tid] + sPart[1][3 * H_ + tid] + sBias[3 * H_ + tid];
                float ig = sigmoidf_(gi), fg = sigmoidf_(gf), og = sigmoidf_(go);
                float c  = fg * s_c[tid] + ig * tanhf(gg);
                s_c[tid] = c;
                s_h[tid] = og * tanhf(c);
            }
            __syncthreads();
        }

        // decoder LSTM weights in registers
        #pragma unroll
        for (int k = 0; k < 32; k++)
            wreg[k] = hf ? dWhh[jg * H_ + k] : dWih[jg * EMB_D_ + k];
        if (tid < 4 * H_) sBias[tid] = dbih[tid] + dbhh[tid];
        if (tid == 0) s_tok = de_batch[bk * S_DE_];     // first token
        __syncthreads();

        // first decoder LSTM -> h for step 1
        if (tid < EMB_D_) sX[tid] = de_emb[(size_t)s_tok * EMB_D_ + tid];
        __syncthreads();
        {
            const float* src = hf ? s_h : sX;
            float p = 0.0f;
            #pragma unroll
            for (int k = 0; k < 32; k++) p += src[k] * wreg[k];
            sPart[hf][jg] = p;
        }
        __syncthreads();
        if (tid < H_) {
            float gi = sPart[0][tid]          + sPart[1][tid]          + sBias[tid];
            float gf = sPart[0][H_ + tid]     + sPart[1][H_ + tid]     + sBias[H_ + tid];
            float gg = sPart[0][2 * H_ + tid] + sPart[1][2 * H_ + tid] + sBias[2 * H_ + tid];
            float go = sPart[0][3 * H_ + tid] + sPart[1][3 * H_ + tid] + sBias[3 * H_ + tid];
            float ig = sigmoidf_(gi), fg = sigmoidf_(gf), og = sigmoidf_(go);
            float c  = fg * s_c[tid] + ig * tanhf(gg);
            s_c[tid] = c;
            float h  = og * tanhf(c);
            s_h[tid] = h;
            __stcg(&g_h[tid * B_ + bk], h);
        }
        if (tid == 0) { __threadfence(); atomicAdd(&g_hdone[1], 1u); }
    }

    const int bq  = tid & 15;       // b-lane (b = bq + 16*i)
    const int vq  = tid >> 4;       // v-octet
    const int vl0 = vq * 8;

    for (int s = 1; s < S_DE_; s++) {
        // ---------- wait for h_s (64 arrivals), copy to smem ----------
        if (tid == 0) { while (ld_acq(&g_hdone[s]) < B_) {} }
        __syncthreads();
        {
            unsigned long long* dst = &sH2[0][0];
            for (int i = tid; i < H_ * B_; i += NTH) {
                float v = __ldcg(&g_h[i]);
                dst[i] = pack2(v, v);
            }
            if (tid < B_) sBest[tid] = 0ull;
        }
        __syncthreads();

        // ---------- logits tile + per-block argmax ----------
        unsigned long long acc[4][4];
        #pragma unroll
        for (int i = 0; i < 4; i++)
            #pragma unroll
            for (int j = 0; j < 4; j++) acc[i][j] = sWb2[vq * 4 + j];

        #pragma unroll 8
        for (int k = 0; k < H_; k++) {
            const unsigned long long* w64 = (const unsigned long long*)&sW[k][0];
            unsigned long long w0 = w64[vq * 4 + 0];
            unsigned long long w1 = w64[vq * 4 + 1];
            unsigned long long w2 = w64[vq * 4 + 2];
            unsigned long long w3 = w64[vq * 4 + 3];
            #pragma unroll
            for (int i = 0; i < 4; i++) {
                unsigned long long hh = sH2[k][bq + 16 * i];
                fma2(acc[i][0], hh, w0);
                fma2(acc[i][1], hh, w1);
                fma2(acc[i][2], hh, w2);
                fma2(acc[i][3], hh, w3);
            }
        }

        if (vl0 < nv) {
            #pragma unroll
            for (int i = 0; i < 4; i++) {
                const int b = bq + 16 * i;
                float2 p0 = unpack2(acc[i][0]);
                float2 p1 = unpack2(acc[i][1]);
                float2 p2 = unpack2(acc[i][2]);
                float2 p3 = unpack2(acc[i][3]);
                float4* orow = (float4*)(out + ((size_t)b * S_DE_ + s) * DE_V_ + v0 + vl0);
                orow[0] = make_float4(p0.x, p0.y, p1.x, p1.y);
                orow[1] = make_float4(p2.x, p2.y, p3.x, p3.y);
                const int vb = v0 + vl0;
                unsigned long long best = amax_key(p0.x, vb);
                unsigned long long k2;
                k2 = amax_key(p0.y, vb + 1); if (k2 > best) best = k2;
                k2 = amax_key(p1.x, vb + 2); if (k2 > best) best = k2;
                k2 = amax_key(p1.y, vb + 3); if (k2 > best) best = k2;
                k2 = amax_key(p2.x, vb + 4); if (k2 > best) best = k2;
                k2 = amax_key(p2.y, vb + 5); if (k2 > best) best = k2;
                k2 = amax_key(p3.x, vb + 6); if (k2 > best) best = k2;
                k2 = amax_key(p3.y, vb + 7); if (k2 > best) best = k2;
                atomicMax(&sBest[b], best);
            }
        }
        __syncthreads();
        // combine into global per-row keys (spread-address device atomics)
        if (tid < B_) atomicMax(&g_best[(size_t)(s * B_ + tid) * 2], sBest[tid]);

        if (s < S_DE_ - 1) {
            __syncthreads();
            if (tid == 0) { __threadfence(); atomicAdd(&g_done[s], 1u); }

            // ---------- LSTM blocks: produce h for step s+1 ----------
            if (bk < B_) {
                if (tid == 0) {
                    while (ld_acq(&g_done[s]) < NBLK) {}
                    unsigned long long key = __ldcg(&g_best[(size_t)(s * B_ + bk) * 2]);
                    s_tok = (int)(0xFFFFFFFFu - (unsigned)(key & 0xFFFFFFFFull));
                }
                __syncthreads();
                if (tid < EMB_D_) sX[tid] = de_emb[(size_t)s_tok * EMB_D_ + tid];
                __syncthreads();
                {
                    const float* src = hf ? s_h : sX;
                    float p = 0.0f;
                    #pragma unroll
                    for (int k = 0; k < 32; k++) p += src[k] * wreg[k];
                    sPart[hf][jg] = p;
                }
                __syncthreads();
                if (tid < H_) {
                    float gi = sPart[0][tid]          + sPart[1][tid]          + sBias[tid];
                    float gf = sPart[0][H_ + tid]     + sPart[1][H_ + tid]     + sBias[H_ + tid];
                    float gg = sPart[0][2 * H_ + tid] + sPart[1][2 * H_ + tid] + sBias[2 * H_ + tid];
                    float go = sPart[0][3 * H_ + tid] + sPart[1][3 * H_ + tid] + sBias[3 * H_ + tid];
                    float ig = sigmoidf_(gi), fg = sigmoidf_(gf), og = sigmoidf_(go);
                    float c  = fg * s_c[tid] + ig * tanhf(gg);
                    s_c[tid] = c;
                    float h  = og * tanhf(c);
                    s_h[tid] = h;
                    __stcg(&g_h[tid * B_ + bk], h);
                }
                if (tid == 0) { __threadfence(); atomicAdd(&g_hdone[s + 1], 1u); }
            }
        }
    }
}

extern "C" void kernel_launch(void* const* d_in, const int* in_sizes, int n_in,
                              void* d_out, int out_size) {
    const int*   en_batch = (const int*)d_in[0];
    const int*   en_lens  = (const int*)d_in[1];
    const int*   de_batch = (const int*)d_in[2];
    const float* en_emb   = (const float*)d_in[3];
    const float* eWih     = (const float*)d_in[4];
    const float* eWhh     = (const float*)d_in[5];
    const float* ebih     = (const float*)d_in[6];
    const float* ebhh     = (const float*)d_in[7];
    const float* de_emb   = (const float*)d_in[8];
    const float* dWih     = (const float*)d_in[9];
    const float* dWhh     = (const float*)d_in[10];
    const float* dbih     = (const float*)d_in[11];
    const float* dbhh     = (const float*)d_in[12];
    const float* fcW      = (const float*)d_in[13];
    const float* fcb      = (const float*)d_in[14];

    seq2seq_kernel<<<NBLK, NTH>>>(en_batch, en_lens, de_batch, en_emb,
                                  eWih, eWhh, ebih, ebhh,
                                  de_emb, dWih, dWhh, dbih, dbhh,
                                  fcW, fcb, (float*)d_out);
}